// round 10
// baseline (speedup 1.0000x reference)
#include <cuda_runtime.h>
#include <cstdint>

// ---------------- problem constants ----------------
#define NB       16
#define N_F      524288
#define N_P      65536
#define EH       2097152
#define E_TOTAL  4194304
#define XP_N     6553600
#define L0       4096
#define L1V      4095
#define L2V      4094
#define KDIM     409400
#define O1       500
#define NCLS     107

// ---------------- packed fp32x2 helpers ----------------
__device__ __forceinline__ double pk2(float lo, float hi) {
    double d; asm("mov.b64 %0, {%1, %2};" : "=d"(d) : "f"(lo), "f"(hi)); return d;
}
__device__ __forceinline__ void upk2(double d, float& lo, float& hi) {
    asm("mov.b64 {%0, %1}, %2;" : "=f"(lo), "=f"(hi) : "d"(d));
}
__device__ __forceinline__ double ffma2(double a, double b, double c) {
    double d; asm("fma.rn.f32x2 %0, %1, %2, %3;" : "=d"(d) : "d"(a), "d"(b), "d"(c)); return d;
}
__device__ __forceinline__ double fadd2(double a, double b) {
    double d; asm("add.rn.f32x2 %0, %1, %2;" : "=d"(d) : "d"(a), "d"(b)); return d;
}

// ---------------- scratch ----------------
__device__ float4 g_xf4[N_F];
__device__ float g_agg[N_P * 4];
__device__ float g_xp[XP_N];
__device__ float g_out1[NB * 100 * L1V];
__device__ float g_out2[NB * 100 * L2V];
__device__ float g_y1[O1 * NB];

// ---------------- zero init ----------------
__global__ void zero_kernel() {
    int i = blockIdx.x * 256 + threadIdx.x;
    if (i < N_P * 4) g_agg[i] = 0.0f;
    if (i < O1 * NB) g_y1[i] = 0.0f;
}

// ---------------- feat: 8192x64 @ 64x192 -> g_xf4 ----------------
#define FEAT_SMEM ((64 * 65 + 192 * 65) * 4)
__global__ __launch_bounds__(256)
void feat_kernel(const float* __restrict__ xsrc,
                 const float* __restrict__ Wfd,
                 const float* __restrict__ bfd) {
    extern __shared__ float sm[];
    float* xs = sm;             // [64][65]
    float* ws = sm + 64 * 65;   // [192][65]
    int t = threadIdx.x;
    int i0 = blockIdx.x << 6;

    for (int idx = t; idx < 4096; idx += 256) {
        int i = idx >> 6, k = idx & 63;
        xs[i * 65 + k] = xsrc[(i0 + i) * 64 + k];
    }
    for (int idx = t; idx < 12288; idx += 256) {
        int j = idx >> 6, k = idx & 63;
        ws[j * 65 + k] = Wfd[idx];
    }
    __syncthreads();

    int tx = t & 15, ty = t >> 4;
    float acc[4][12];
#pragma unroll
    for (int ii = 0; ii < 4; ii++)
#pragma unroll
        for (int jj = 0; jj < 12; jj++) acc[ii][jj] = 0.0f;

    for (int k = 0; k < 64; k++) {
        float xv[4], wv[12];
#pragma unroll
        for (int ii = 0; ii < 4; ii++) xv[ii] = xs[(ty * 4 + ii) * 65 + k];
#pragma unroll
        for (int jj = 0; jj < 12; jj++) wv[jj] = ws[(tx * 12 + jj) * 65 + k];
#pragma unroll
        for (int ii = 0; ii < 4; ii++)
#pragma unroll
            for (int jj = 0; jj < 12; jj++)
                acc[ii][jj] = fmaf(xv[ii], wv[jj], acc[ii][jj]);
    }

    int j0 = tx * 12;
#pragma unroll
    for (int ii = 0; ii < 4; ii++) {
        int i = i0 + ty * 4 + ii;
#pragma unroll
        for (int rr = 0; rr < 4; rr++) {
            int r = i * 64 + tx * 4 + rr;
            g_xf4[r] = make_float4(
                acc[ii][rr * 3 + 0] + __ldg(bfd + j0 + rr * 3 + 0),
                acc[ii][rr * 3 + 1] + __ldg(bfd + j0 + rr * 3 + 1),
                acc[ii][rr * 3 + 2] + __ldg(bfd + j0 + rr * 3 + 2),
                0.0f);
        }
    }
}

// ---------------- edge aggregation ----------------
__global__ void edge_kernel(const int* __restrict__ ei) {
    int e2 = blockIdx.x * 256 + threadIdx.x;
    int4 s4 = *reinterpret_cast<const int4*>(ei + 4 * e2);
    int4 d4 = *reinterpret_cast<const int4*>(ei + E_TOTAL + 4 * e2);
    float4 v0 = g_xf4[s4.x];
    float4 v1 = g_xf4[s4.z];
    float* a0 = g_agg + 4 * d4.x;
    float* a1 = g_agg + 4 * d4.z;
    asm volatile("red.global.add.v4.f32 [%0], {%1, %2, %3, %4};"
                 :: "l"(a0), "f"(v0.x), "f"(v0.y), "f"(v0.z), "f"(1.0f) : "memory");
    asm volatile("red.global.add.v4.f32 [%0], {%1, %2, %3, %4};"
                 :: "l"(a1), "f"(v1.x), "f"(v1.y), "f"(v1.z), "f"(1.0f) : "memory");
}

// ---------------- node update ----------------
__global__ __launch_bounds__(256)
void node_kernel(const float* __restrict__ xdst,
                 const float* __restrict__ Wl1,
                 const float* __restrict__ bl1,
                 const float* __restrict__ Wr1) {
    __shared__ float swl[300], swr[300], sb[100];
    int t = threadIdx.x;
    for (int idx = t; idx < 300; idx += 256) { swl[idx] = Wl1[idx]; swr[idx] = Wr1[idx]; }
    if (t < 100) sb[t] = bl1[t];
    __syncthreads();

    int gid = blockIdx.x * 256 + t;
    int n = gid / 25;
    int c0 = (gid - n * 25) * 4;
    float4 a = *reinterpret_cast<const float4*>(&g_agg[n * 4]);
    float inv = __fdividef(1.0f, fmaxf(a.w, 1.0f));
    float m0 = a.x * inv, m1 = a.y * inv, m2 = a.z * inv;
    const float* xd = xdst + 3 * n;
    float d0 = xd[0], d1 = xd[1], d2 = xd[2];
    float r[4];
#pragma unroll
    for (int cc = 0; cc < 4; cc++) {
        int c = c0 + cc;
        float v = sb[c];
        v = fmaf(m0, swl[c * 3 + 0], v);
        v = fmaf(m1, swl[c * 3 + 1], v);
        v = fmaf(m2, swl[c * 3 + 2], v);
        v = fmaf(d0, swr[c * 3 + 0], v);
        v = fmaf(d1, swr[c * 3 + 1], v);
        v = fmaf(d2, swr[c * 3 + 2], v);
        r[cc] = fmaxf(v, 0.0f);
    }
    *reinterpret_cast<float4*>(&g_xp[n * 100 + c0]) =
        make_float4(r[0], r[1], r[2], r[3]);
}

// ---------------- conv (k=2, 100->100), packed f32x2; 2 blocks/SM ----------------
#define CONV_SMEM ((100 * 202 + 100 * 68) * 4)
__global__ __launch_bounds__(200, 2)
void conv_kernel(const float* __restrict__ in, const float* __restrict__ W,
                 float* __restrict__ out, int Lin, int Lout) {
    extern __shared__ float sm[];
    float* ws = sm;               // [o][202]
    float* xs = sm + 100 * 202;   // [i][68]
    int b  = blockIdx.x;
    int h0 = blockIdx.y << 6;
    int t  = threadIdx.x;

    for (int idx = t; idx < 20000; idx += 200) {
        int o = idx / 200;
        ws[o * 202 + (idx - o * 200)] = W[idx];
    }
    int nj = Lin - h0; if (nj > 65) nj = 65;
    const float* inb = in + b * 100 * Lin + h0;
    for (int idx = t; idx < 6800; idx += 200) {
        int i = idx / 68;
        int j = idx - i * 68;
        xs[idx] = (j < nj) ? inb[i * Lin + j] : 0.0f;
    }
    __syncthreads();

    int og = t >> 3, ht = t & 7;
    int o0 = og << 2, hh = ht << 3;
    double acc2[4][8];
#pragma unroll
    for (int oo = 0; oo < 4; oo++)
#pragma unroll
        for (int j = 0; j < 8; j++) acc2[oo][j] = 0.0;

    for (int i = 0; i < 100; i++) {
        const float* xr = xs + i * 68 + hh;
        float4 xA = *reinterpret_cast<const float4*>(xr);
        float4 xB = *reinterpret_cast<const float4*>(xr + 4);
        float x8 = xr[8];
        double xp[8];
        xp[0] = pk2(xA.x, xA.y); xp[1] = pk2(xA.y, xA.z);
        xp[2] = pk2(xA.z, xA.w); xp[3] = pk2(xA.w, xB.x);
        xp[4] = pk2(xB.x, xB.y); xp[5] = pk2(xB.y, xB.z);
        xp[6] = pk2(xB.z, xB.w); xp[7] = pk2(xB.w, x8);
#pragma unroll
        for (int oo = 0; oo < 4; oo++) {
            double wp = *reinterpret_cast<const double*>(&ws[(o0 + oo) * 202 + i * 2]);
#pragma unroll
            for (int j = 0; j < 8; j++)
                acc2[oo][j] = ffma2(wp, xp[j], acc2[oo][j]);
        }
    }

    float* outb = out + b * 100 * Lout;
#pragma unroll
    for (int oo = 0; oo < 4; oo++)
#pragma unroll
        for (int j = 0; j < 8; j++) {
            int h = h0 + hh + j;
            if (h < Lout) {
                float lo, hi; upk2(acc2[oo][j], lo, hi);
                outb[(o0 + oo) * Lout + h] = fmaxf(lo + hi, 0.0f);
            }
        }
}

// ---------------- dense1 v7: O_w=8 via two b-half passes -> smem traffic halved --
// grid (400 k-chunks, 8 o-tiles of 64). block 256 = 8 warps x 8 o. lane = k.
// Per pass: acc2[8][4] packed (64 regs, reused across passes). W pass-B hits L2.
#define D1_SMEM (1024 * 20 * 4)
__global__ __launch_bounds__(256, 2)
void dense1_kernel(const float* __restrict__ x2, const float* __restrict__ W) {
    extern __shared__ float xs[];   // [1024][20]
    int t = threadIdx.x;
    int k0 = blockIdx.x << 10;
    int KN = KDIM - k0; if (KN > 1024) KN = 1024;

    // stage x transposed, conflict-free STS (b = idx & 15)
    for (int idx = t; idx < 4096; idx += 256) {
        int b  = idx & 15;
        int kk = (idx >> 4) << 2;
        float4 v = make_float4(0.f, 0.f, 0.f, 0.f);
        if (kk < KN)
            v = *reinterpret_cast<const float4*>(x2 + (size_t)b * KDIM + k0 + kk);
        xs[(kk + 0) * 20 + b] = v.x;
        xs[(kk + 1) * 20 + b] = v.y;
        xs[(kk + 2) * 20 + b] = v.z;
        xs[(kk + 3) * 20 + b] = v.w;
    }
    __syncthreads();

    int wid = t >> 5, lane = t & 31;
    int o0 = (blockIdx.y << 6) + (wid << 3);   // 8 o-rows per warp

    // 32-bit row offsets (clamped) relative to W + k0
    const float* wbase = W + k0;
    int offs[8];
#pragma unroll
    for (int o = 0; o < 8; o++) {
        int r = o0 + o; if (r > O1 - 1) r = O1 - 1;
        offs[o] = r * KDIM;
    }

#pragma unroll 1
    for (int p = 0; p < 2; p++) {              // b-half passes (b = p*8 .. p*8+7)
        double acc2[8][4];
#pragma unroll
        for (int o = 0; o < 8; o++)
#pragma unroll
            for (int bp = 0; bp < 4; bp++) acc2[o][bp] = 0.0;

        // 2-deep W prefetch
        float wbuf[2][8];
#pragma unroll
        for (int q = 0; q < 2; q++) {
            int k = lane + (q << 5);
#pragma unroll
            for (int o = 0; o < 8; o++)
                wbuf[q][o] = (k < KN) ? __ldg(wbase + offs[o] + k) : 0.0f;
        }

#pragma unroll 2
        for (int it = 0; it < 32; it++) {
            int slot = it & 1;
            int k = lane + (it << 5);
            int kn = k + 64;

            // x pairs for this half: 2 x LDS.128, already pair-packed
            const double2* xr = reinterpret_cast<const double2*>(&xs[k * 20 + p * 8]);
            double2 xA = xr[0], xB = xr[1];
            double xp[4] = {xA.x, xA.y, xB.x, xB.y};

            // process o in two subgroups of 4 (bounds wd live range)
#pragma unroll
            for (int g = 0; g < 2; g++) {
                double wd[4];
#pragma unroll
                for (int o = 0; o < 4; o++) {
                    float wv = wbuf[slot][g * 4 + o];
                    wd[o] = pk2(wv, wv);
                }
#pragma unroll
                for (int o = 0; o < 4; o++)
#pragma unroll
                    for (int bp = 0; bp < 4; bp++)
                        acc2[g * 4 + o][bp] = ffma2(wd[o], xp[bp], acc2[g * 4 + o][bp]);
            }
            // refill slot for it+2
#pragma unroll
            for (int o = 0; o < 8; o++)
                wbuf[slot][o] = (kn < KN) ? __ldg(wbase + offs[o] + kn) : 0.0f;
        }

        // reduce 32 packed values (a = o*4 + bp) across 32 lanes; lane ends owning a = lane
        double s2[32];
#pragma unroll
        for (int a = 0; a < 32; a++) s2[a] = acc2[a >> 2][a & 3];
        int n = 32;
#pragma unroll
        for (int d = 16; d >= 1; d >>= 1) {
            n >>= 1;
            bool hiSel = (lane & d) != 0;
#pragma unroll
            for (int i = 0; i < 16; i++) {
                if (i >= n) break;
                double send = hiSel ? s2[i] : s2[i + n];
                double recv = __shfl_xor_sync(0xffffffffu, send, d);
                double keep = hiSel ? s2[i + n] : s2[i];
                s2[i] = fadd2(keep, recv);
            }
        }
        int orow = o0 + (lane >> 2);
        if (orow < O1) {
            float lo, hi; upk2(s2[0], lo, hi);
            float* addr = &g_y1[orow * 16 + p * 8 + 2 * (lane & 3)];
            asm volatile("red.global.add.v2.f32 [%0], {%1, %2};"
                         :: "l"(addr), "f"(lo), "f"(hi) : "memory");
        }
    }
}

// ---------------- dense2 + softmax ----------------
__global__ void dense2_kernel(const float* __restrict__ Wd2, float* __restrict__ out) {
    __shared__ float ys[O1];
    __shared__ float red[128];
    int b = blockIdx.x, t = threadIdx.x;
    for (int o = t; o < O1; o += 128) ys[o] = fmaxf(g_y1[o * 16 + b], 0.0f);
    __syncthreads();

    float logit = -1e30f;
    if (t < NCLS) {
        float s = 0.0f;
        const float* wr = Wd2 + t * O1;
        for (int o = 0; o < O1; o++) s = fmaf(ys[o], __ldg(wr + o), s);
        logit = s;
    }
    red[t] = logit;
    __syncthreads();
    for (int s = 64; s > 0; s >>= 1) {
        if (t < s) red[t] = fmaxf(red[t], red[t + s]);
        __syncthreads();
    }
    float mx = red[0];
    __syncthreads();
    float e = (t < NCLS) ? expf(logit - mx) : 0.0f;
    red[t] = e;
    __syncthreads();
    for (int s = 64; s > 0; s >>= 1) {
        if (t < s) red[t] += red[t + s];
        __syncthreads();
    }
    float sum = red[0];
    if (t < NCLS) out[b * NCLS + t] = e / sum;
}

// ---------------- launch ----------------
extern "C" void kernel_launch(void* const* d_in, const int* in_sizes, int n_in,
                              void* d_out, int out_size) {
    const float* x_src = (const float*)d_in[0];
    const float* x_dst = (const float*)d_in[1];
    const int*   ei    = (const int*)  d_in[2];
    const float* Wfd   = (const float*)d_in[3];
    const float* bfd   = (const float*)d_in[4];
    const float* Wl1   = (const float*)d_in[5];
    const float* bl1   = (const float*)d_in[6];
    const float* Wr1   = (const float*)d_in[7];
    const float* Wc1   = (const float*)d_in[11];
    const float* Wc2   = (const float*)d_in[12];
    const float* Wd1   = (const float*)d_in[13];
    const float* Wd2   = (const float*)d_in[14];
    float* out = (float*)d_out;

    float *p_xp, *p_o1, *p_o2;
    cudaGetSymbolAddress((void**)&p_xp, g_xp);
    cudaGetSymbolAddress((void**)&p_o1, g_out1);
    cudaGetSymbolAddress((void**)&p_o2, g_out2);

    cudaFuncSetAttribute(feat_kernel,   cudaFuncAttributeMaxDynamicSharedMemorySize, FEAT_SMEM);
    cudaFuncSetAttribute(conv_kernel,   cudaFuncAttributeMaxDynamicSharedMemorySize, CONV_SMEM);
    cudaFuncSetAttribute(conv_kernel,   cudaFuncAttributePreferredSharedMemoryCarveout, 100);
    cudaFuncSetAttribute(dense1_kernel, cudaFuncAttributeMaxDynamicSharedMemorySize, D1_SMEM);
    cudaFuncSetAttribute(dense1_kernel, cudaFuncAttributePreferredSharedMemoryCarveout, 100);

    zero_kernel<<<(N_P * 4 + 255) / 256, 256>>>();
    feat_kernel<<<128, 256, FEAT_SMEM>>>(x_src, Wfd, bfd);
    edge_kernel<<<4096, 256>>>(ei);
    node_kernel<<<6400, 256>>>(x_dst, Wl1, bl1, Wr1);
    conv_kernel<<<dim3(16, 64), 200, CONV_SMEM>>>(p_xp, Wc1, p_o1, L0, L1V);
    conv_kernel<<<dim3(16, 64), 200, CONV_SMEM>>>(p_o1, Wc2, p_o2, L1V, L2V);
    dense1_kernel<<<dim3(400, 8), 256, D1_SMEM>>>(p_o2, Wd1);
    dense2_kernel<<<NB, 128>>>(Wd2, out);
}

// round 11
// speedup vs baseline: 1.0368x; 1.0368x over previous
#include <cuda_runtime.h>
#include <cstdint>

// ---------------- problem constants ----------------
#define NB       16
#define N_F      524288
#define N_P      65536
#define EH       2097152
#define E_TOTAL  4194304
#define L0       4096
#define L1V      4095
#define L2V      4094
#define KDIM     409400
#define O1       500
#define NCLS     107

// ---------------- packed fp32x2 helpers ----------------
__device__ __forceinline__ double pk2(float lo, float hi) {
    double d; asm("mov.b64 %0, {%1, %2};" : "=d"(d) : "f"(lo), "f"(hi)); return d;
}
__device__ __forceinline__ void upk2(double d, float& lo, float& hi) {
    asm("mov.b64 {%0, %1}, %2;" : "=f"(lo), "=f"(hi) : "d"(d));
}
__device__ __forceinline__ double ffma2(double a, double b, double c) {
    double d; asm("fma.rn.f32x2 %0, %1, %2, %3;" : "=d"(d) : "d"(a), "d"(b), "d"(c)); return d;
}
__device__ __forceinline__ double fadd2(double a, double b) {
    double d; asm("add.rn.f32x2 %0, %1, %2;" : "=d"(d) : "d"(a), "d"(b)); return d;
}

// ---------------- scratch ----------------
__device__ float4 g_xf4[N_F];
__device__ float g_agg[N_P * 4];
__device__ float g_out1[NB * 100 * L1V];
__device__ float g_out2[NB * 100 * L2V];
__device__ float g_y1[O1 * NB];

// ---------------- feat (+ fused zero-init): 8192x64 @ 64x192 -> g_xf4 ------------
#define FEAT_SMEM ((64 * 65 + 192 * 65) * 4)
__global__ __launch_bounds__(256)
void feat_kernel(const float* __restrict__ xsrc,
                 const float* __restrict__ Wfd,
                 const float* __restrict__ bfd) {
    // fused zeroing (completes before edge/dense1 launch, stream-ordered)
    int t0 = blockIdx.x * 256 + threadIdx.x;        // 0..32767
#pragma unroll
    for (int z = t0; z < N_P * 4; z += 32768) g_agg[z] = 0.0f;
    if (t0 < O1 * NB) g_y1[t0] = 0.0f;

    extern __shared__ float sm[];
    float* xs = sm;             // [64][65]
    float* ws = sm + 64 * 65;   // [192][65]
    int t = threadIdx.x;
    int i0 = blockIdx.x << 6;

    for (int idx = t; idx < 4096; idx += 256) {
        int i = idx >> 6, k = idx & 63;
        xs[i * 65 + k] = xsrc[(i0 + i) * 64 + k];
    }
    for (int idx = t; idx < 12288; idx += 256) {
        int j = idx >> 6, k = idx & 63;
        ws[j * 65 + k] = Wfd[idx];
    }
    __syncthreads();

    int tx = t & 15, ty = t >> 4;
    float acc[4][12];
#pragma unroll
    for (int ii = 0; ii < 4; ii++)
#pragma unroll
        for (int jj = 0; jj < 12; jj++) acc[ii][jj] = 0.0f;

    for (int k = 0; k < 64; k++) {
        float xv[4], wv[12];
#pragma unroll
        for (int ii = 0; ii < 4; ii++) xv[ii] = xs[(ty * 4 + ii) * 65 + k];
#pragma unroll
        for (int jj = 0; jj < 12; jj++) wv[jj] = ws[(tx * 12 + jj) * 65 + k];
#pragma unroll
        for (int ii = 0; ii < 4; ii++)
#pragma unroll
            for (int jj = 0; jj < 12; jj++)
                acc[ii][jj] = fmaf(xv[ii], wv[jj], acc[ii][jj]);
    }

    int j0 = tx * 12;
#pragma unroll
    for (int ii = 0; ii < 4; ii++) {
        int i = i0 + ty * 4 + ii;
#pragma unroll
        for (int rr = 0; rr < 4; rr++) {
            int r = i * 64 + tx * 4 + rr;
            g_xf4[r] = make_float4(
                acc[ii][rr * 3 + 0] + __ldg(bfd + j0 + rr * 3 + 0),
                acc[ii][rr * 3 + 1] + __ldg(bfd + j0 + rr * 3 + 1),
                acc[ii][rr * 3 + 2] + __ldg(bfd + j0 + rr * 3 + 2),
                0.0f);
        }
    }
}

// ---------------- edge aggregation ----------------
__global__ void edge_kernel(const int* __restrict__ ei) {
    int e2 = blockIdx.x * 256 + threadIdx.x;
    int4 s4 = *reinterpret_cast<const int4*>(ei + 4 * e2);
    int4 d4 = *reinterpret_cast<const int4*>(ei + E_TOTAL + 4 * e2);
    float4 v0 = g_xf4[s4.x];
    float4 v1 = g_xf4[s4.z];
    float* a0 = g_agg + 4 * d4.x;
    float* a1 = g_agg + 4 * d4.z;
    asm volatile("red.global.add.v4.f32 [%0], {%1, %2, %3, %4};"
                 :: "l"(a0), "f"(v0.x), "f"(v0.y), "f"(v0.z), "f"(1.0f) : "memory");
    asm volatile("red.global.add.v4.f32 [%0], {%1, %2, %3, %4};"
                 :: "l"(a1), "f"(v1.x), "f"(v1.y), "f"(v1.z), "f"(1.0f) : "memory");
}

// ---------------- conv1 (node-update FUSED; no g_xp round-trip) -------------------
// x[b][i][h] = x_p.flat[b*409600 + i*4096 + h]; flat f -> node f/100, channel f%100.
#define C1_SMEM ((100 * 202 + 100 * 68 + 704) * 4)
__global__ __launch_bounds__(200, 2)
void conv1_kernel(const float* __restrict__ xdst,
                  const float* __restrict__ Wl1,
                  const float* __restrict__ bl1,
                  const float* __restrict__ Wr1,
                  const float* __restrict__ Wc1,
                  float* __restrict__ out) {
    extern __shared__ float sm[];
    float* ws  = sm;                 // [o][202]
    float* xs  = sm + 20200;         // [i][68]
    float* swl = sm + 27000;         // 300
    float* swr = swl + 300;          // 300
    float* sb  = swr + 300;          // 100
    int b  = blockIdx.x;
    int h0 = blockIdx.y << 6;
    int t  = threadIdx.x;

    for (int idx = t; idx < 20000; idx += 200) {
        int o = idx / 200;
        ws[o * 202 + (idx - o * 200)] = Wc1[idx];
    }
    for (int idx = t; idx < 300; idx += 200) { swl[idx] = Wl1[idx]; swr[idx] = Wr1[idx]; }
    if (t < 100) sb[t] = bl1[t];
    __syncthreads();

    // build x-tile directly from aggregates (node update fused)
    int nj = L0 - h0; if (nj > 65) nj = 65;
    for (int idx = t; idx < 6500; idx += 200) {
        int i = idx / 65, j = idx - i * 65;
        float v = 0.0f;
        if (j < nj) {
            int q  = i * 4096 + h0 + j;          // flat within batch
            int nl = q / 100;
            int c  = q - nl * 100;
            int n  = b * 4096 + nl;
            float4 a = *reinterpret_cast<const float4*>(&g_agg[n * 4]);
            float inv = __fdividef(1.0f, fmaxf(a.w, 1.0f));
            const float* xd = xdst + 3 * n;
            float m0 = a.x * inv, m1 = a.y * inv, m2 = a.z * inv;
            v = sb[c];
            v = fmaf(m0, swl[c * 3 + 0], v);
            v = fmaf(m1, swl[c * 3 + 1], v);
            v = fmaf(m2, swl[c * 3 + 2], v);
            v = fmaf(xd[0], swr[c * 3 + 0], v);
            v = fmaf(xd[1], swr[c * 3 + 1], v);
            v = fmaf(xd[2], swr[c * 3 + 2], v);
            v = fmaxf(v, 0.0f);
        }
        xs[i * 68 + j] = v;
    }
    __syncthreads();

    int og = t >> 3, ht = t & 7;
    int o0 = og << 2, hh = ht << 3;
    double acc2[4][8];
#pragma unroll
    for (int oo = 0; oo < 4; oo++)
#pragma unroll
        for (int j = 0; j < 8; j++) acc2[oo][j] = 0.0;

    for (int i = 0; i < 100; i++) {
        const float* xr = xs + i * 68 + hh;
        float4 xA = *reinterpret_cast<const float4*>(xr);
        float4 xB = *reinterpret_cast<const float4*>(xr + 4);
        float x8 = xr[8];
        double xp[8];
        xp[0] = pk2(xA.x, xA.y); xp[1] = pk2(xA.y, xA.z);
        xp[2] = pk2(xA.z, xA.w); xp[3] = pk2(xA.w, xB.x);
        xp[4] = pk2(xB.x, xB.y); xp[5] = pk2(xB.y, xB.z);
        xp[6] = pk2(xB.z, xB.w); xp[7] = pk2(xB.w, x8);
#pragma unroll
        for (int oo = 0; oo < 4; oo++) {
            double wp = *reinterpret_cast<const double*>(&ws[(o0 + oo) * 202 + i * 2]);
#pragma unroll
            for (int j = 0; j < 8; j++)
                acc2[oo][j] = ffma2(wp, xp[j], acc2[oo][j]);
        }
    }

    float* outb = out + b * 100 * L1V;
#pragma unroll
    for (int oo = 0; oo < 4; oo++)
#pragma unroll
        for (int j = 0; j < 8; j++) {
            int h = h0 + hh + j;
            if (h < L1V) {
                float lo, hi; upk2(acc2[oo][j], lo, hi);
                outb[(o0 + oo) * L1V + h] = fmaxf(lo + hi, 0.0f);
            }
        }
}

// ---------------- conv2 (k=2, 100->100), packed f32x2 ----------------------------
#define CONV_SMEM ((100 * 202 + 100 * 68) * 4)
__global__ __launch_bounds__(200, 2)
void conv_kernel(const float* __restrict__ in, const float* __restrict__ W,
                 float* __restrict__ out, int Lin, int Lout) {
    extern __shared__ float sm[];
    float* ws = sm;               // [o][202]
    float* xs = sm + 100 * 202;   // [i][68]
    int b  = blockIdx.x;
    int h0 = blockIdx.y << 6;
    int t  = threadIdx.x;

    for (int idx = t; idx < 20000; idx += 200) {
        int o = idx / 200;
        ws[o * 202 + (idx - o * 200)] = W[idx];
    }
    int nj = Lin - h0; if (nj > 65) nj = 65;
    const float* inb = in + b * 100 * Lin + h0;
    for (int idx = t; idx < 6800; idx += 200) {
        int i = idx / 68;
        int j = idx - i * 68;
        xs[idx] = (j < nj) ? inb[i * Lin + j] : 0.0f;
    }
    __syncthreads();

    int og = t >> 3, ht = t & 7;
    int o0 = og << 2, hh = ht << 3;
    double acc2[4][8];
#pragma unroll
    for (int oo = 0; oo < 4; oo++)
#pragma unroll
        for (int j = 0; j < 8; j++) acc2[oo][j] = 0.0;

    for (int i = 0; i < 100; i++) {
        const float* xr = xs + i * 68 + hh;
        float4 xA = *reinterpret_cast<const float4*>(xr);
        float4 xB = *reinterpret_cast<const float4*>(xr + 4);
        float x8 = xr[8];
        double xp[8];
        xp[0] = pk2(xA.x, xA.y); xp[1] = pk2(xA.y, xA.z);
        xp[2] = pk2(xA.z, xA.w); xp[3] = pk2(xA.w, xB.x);
        xp[4] = pk2(xB.x, xB.y); xp[5] = pk2(xB.y, xB.z);
        xp[6] = pk2(xB.z, xB.w); xp[7] = pk2(xB.w, x8);
#pragma unroll
        for (int oo = 0; oo < 4; oo++) {
            double wp = *reinterpret_cast<const double*>(&ws[(o0 + oo) * 202 + i * 2]);
#pragma unroll
            for (int j = 0; j < 8; j++)
                acc2[oo][j] = ffma2(wp, xp[j], acc2[oo][j]);
        }
    }

    float* outb = out + b * 100 * Lout;
#pragma unroll
    for (int oo = 0; oo < 4; oo++)
#pragma unroll
        for (int j = 0; j < 8; j++) {
            int h = h0 + hh + j;
            if (h < Lout) {
                float lo, hi; upk2(acc2[oo][j], lo, hi);
                outb[(o0 + oo) * Lout + h] = fmaxf(lo + hi, 0.0f);
            }
        }
}

// ---------------- dense1 v4 (best measured: 655us config, verbatim) ---------------
#define D1_SMEM (1024 * 20 * 4)
__global__ __launch_bounds__(256, 2)
void dense1_kernel(const float* __restrict__ x2, const float* __restrict__ W) {
    extern __shared__ float xs[];   // [1024][20]
    int t = threadIdx.x;
    int k0 = blockIdx.x << 10;
    int KN = KDIM - k0; if (KN > 1024) KN = 1024;

    for (int idx = t; idx < 4096; idx += 256) {
        int b  = idx & 15;
        int kk = (idx >> 4) << 2;
        float4 v = make_float4(0.f, 0.f, 0.f, 0.f);
        if (kk < KN)
            v = *reinterpret_cast<const float4*>(x2 + (size_t)b * KDIM + k0 + kk);
        xs[(kk + 0) * 20 + b] = v.x;
        xs[(kk + 1) * 20 + b] = v.y;
        xs[(kk + 2) * 20 + b] = v.z;
        xs[(kk + 3) * 20 + b] = v.w;
    }
    __syncthreads();

    int wid = t >> 5, lane = t & 31;
    int o0 = (blockIdx.y << 5) + (wid << 2);
    if (o0 >= O1) return;

    double acc2[4][8];
#pragma unroll
    for (int o = 0; o < 4; o++)
#pragma unroll
        for (int bp = 0; bp < 8; bp++) acc2[o][bp] = 0.0;

    const float* wbase = W + (size_t)o0 * KDIM + k0;

    float wbuf[4][4];
#pragma unroll
    for (int p = 0; p < 4; p++) {
        int k = lane + (p << 5);
#pragma unroll
        for (int o = 0; o < 4; o++)
            wbuf[p][o] = (k < KN) ? __ldg(wbase + (size_t)o * KDIM + k) : 0.0f;
    }

#pragma unroll 4
    for (int it = 0; it < 32; it++) {
        int slot = it & 3;
        int k = lane + (it << 5);

        double wd[4];
#pragma unroll
        for (int o = 0; o < 4; o++) wd[o] = pk2(wbuf[slot][o], wbuf[slot][o]);

        int kn = k + 128;
#pragma unroll
        for (int o = 0; o < 4; o++)
            wbuf[slot][o] = (kn < KN) ? __ldg(wbase + (size_t)o * KDIM + kn) : 0.0f;

        const double2* xrow = reinterpret_cast<const double2*>(&xs[k * 20]);
        double2 x01 = xrow[0], x23 = xrow[1], x45 = xrow[2], x67 = xrow[3];
        double xp[8] = {x01.x, x01.y, x23.x, x23.y, x45.x, x45.y, x67.x, x67.y};

#pragma unroll
        for (int o = 0; o < 4; o++)
#pragma unroll
            for (int bp = 0; bp < 8; bp++)
                acc2[o][bp] = ffma2(wd[o], xp[bp], acc2[o][bp]);
    }

    double s2[32];
#pragma unroll
    for (int a = 0; a < 32; a++) s2[a] = acc2[a >> 3][a & 7];
    int n = 32;
#pragma unroll
    for (int d = 16; d >= 1; d >>= 1) {
        n >>= 1;
        bool hiSel = (lane & d) != 0;
#pragma unroll
        for (int i = 0; i < 16; i++) {
            if (i >= n) break;
            double send = hiSel ? s2[i] : s2[i + n];
            double recv = __shfl_xor_sync(0xffffffffu, send, d);
            double keep = hiSel ? s2[i + n] : s2[i];
            s2[i] = fadd2(keep, recv);
        }
    }
    float lo, hi; upk2(s2[0], lo, hi);
    float* addr = &g_y1[(o0 + (lane >> 3)) * 16 + 2 * (lane & 7)];
    asm volatile("red.global.add.v2.f32 [%0], {%1, %2};"
                 :: "l"(addr), "f"(lo), "f"(hi) : "memory");
}

// ---------------- dense2 + softmax ----------------
__global__ void dense2_kernel(const float* __restrict__ Wd2, float* __restrict__ out) {
    __shared__ float ys[O1];
    __shared__ float red[128];
    int b = blockIdx.x, t = threadIdx.x;
    for (int o = t; o < O1; o += 128) ys[o] = fmaxf(g_y1[o * 16 + b], 0.0f);
    __syncthreads();

    float logit = -1e30f;
    if (t < NCLS) {
        float s = 0.0f;
        const float* wr = Wd2 + t * O1;
        for (int o = 0; o < O1; o++) s = fmaf(ys[o], __ldg(wr + o), s);
        logit = s;
    }
    red[t] = logit;
    __syncthreads();
    for (int s = 64; s > 0; s >>= 1) {
        if (t < s) red[t] = fmaxf(red[t], red[t + s]);
        __syncthreads();
    }
    float mx = red[0];
    __syncthreads();
    float e = (t < NCLS) ? expf(logit - mx) : 0.0f;
    red[t] = e;
    __syncthreads();
    for (int s = 64; s > 0; s >>= 1) {
        if (t < s) red[t] += red[t + s];
        __syncthreads();
    }
    float sum = red[0];
    if (t < NCLS) out[b * NCLS + t] = e / sum;
}

// ---------------- launch ----------------
extern "C" void kernel_launch(void* const* d_in, const int* in_sizes, int n_in,
                              void* d_out, int out_size) {
    const float* x_src = (const float*)d_in[0];
    const float* x_dst = (const float*)d_in[1];
    const int*   ei    = (const int*)  d_in[2];
    const float* Wfd   = (const float*)d_in[3];
    const float* bfd   = (const float*)d_in[4];
    const float* Wl1   = (const float*)d_in[5];
    const float* bl1   = (const float*)d_in[6];
    const float* Wr1   = (const float*)d_in[7];
    const float* Wc1   = (const float*)d_in[11];
    const float* Wc2   = (const float*)d_in[12];
    const float* Wd1   = (const float*)d_in[13];
    const float* Wd2   = (const float*)d_in[14];
    float* out = (float*)d_out;

    float *p_o1, *p_o2;
    cudaGetSymbolAddress((void**)&p_o1, g_out1);
    cudaGetSymbolAddress((void**)&p_o2, g_out2);

    cudaFuncSetAttribute(feat_kernel,   cudaFuncAttributeMaxDynamicSharedMemorySize, FEAT_SMEM);
    cudaFuncSetAttribute(conv1_kernel,  cudaFuncAttributeMaxDynamicSharedMemorySize, C1_SMEM);
    cudaFuncSetAttribute(conv1_kernel,  cudaFuncAttributePreferredSharedMemoryCarveout, 100);
    cudaFuncSetAttribute(conv_kernel,   cudaFuncAttributeMaxDynamicSharedMemorySize, CONV_SMEM);
    cudaFuncSetAttribute(conv_kernel,   cudaFuncAttributePreferredSharedMemoryCarveout, 100);
    cudaFuncSetAttribute(dense1_kernel, cudaFuncAttributeMaxDynamicSharedMemorySize, D1_SMEM);
    cudaFuncSetAttribute(dense1_kernel, cudaFuncAttributePreferredSharedMemoryCarveout, 100);

    feat_kernel<<<128, 256, FEAT_SMEM>>>(x_src, Wfd, bfd);              // #1 (+zero)
    edge_kernel<<<4096, 256>>>(ei);                                     // #2
    conv1_kernel<<<dim3(16, 64), 200, C1_SMEM>>>(x_dst, Wl1, bl1, Wr1, Wc1, p_o1); // #3
    conv_kernel<<<dim3(16, 64), 200, CONV_SMEM>>>(p_o1, Wc2, p_o2, L1V, L2V);      // #4
    dense1_kernel<<<dim3(400, 16), 256, D1_SMEM>>>(p_o2, Wd1);          // #5
    dense2_kernel<<<NB, 128>>>(Wd2, out);                               // #6
}